// round 4
// baseline (speedup 1.0000x reference)
#include <cuda_runtime.h>

// Problem constants
#define BB 2
#define NN 2048
#define CC 1024
#define HH 16
#define HD 64
#define MROWS (BB*NN)        // 4096
#define SCALE 0.125f         // hd^-0.5
#define NEGINF (-1.0e30f)

typedef unsigned long long u64;

// ---- packed f32x2 helpers (sm_100+) ----
__device__ __forceinline__ u64 pk2(float lo, float hi) {
    u64 r; asm("mov.b64 %0, {%1, %2};" : "=l"(r) : "f"(lo), "f"(hi)); return r;
}
__device__ __forceinline__ void upk2(float& lo, float& hi, u64 v) {
    asm("mov.b64 {%0, %1}, %2;" : "=f"(lo), "=f"(hi) : "l"(v));
}
__device__ __forceinline__ void fma2(u64& d, u64 a, u64 b) {
    asm("fma.rn.f32x2 %0, %1, %2, %0;" : "+l"(d) : "l"(a), "l"(b));
}
__device__ __forceinline__ u64 mul2(u64 a, u64 b) {
    u64 r; asm("mul.rn.f32x2 %0, %1, %2;" : "=l"(r) : "l"(a), "l"(b)); return r;
}
__device__ __forceinline__ u64 f4lo(float4 f) { return pk2(f.x, f.y); }
__device__ __forceinline__ u64 f4hi(float4 f) { return pk2(f.z, f.w); }

// Scratch for projected+roped Q,K,V in [B,N,H*hd] layout (row = b*N+n, col = h*64+d)
__device__ float g_proj[3][(size_t)MROWS * CC];

// ---------------------------------------------------------------------------
// Kernel 1: fused projection  Y = X @ W^T + b, with RoPE epilogue for Q,K.
// 128x128 tile, BK=16, 256 threads, 8x8 per thread, f32x2 inner product.
// Software-pipelined: gmem loads for step kt+1 issued before compute of kt.
// ---------------------------------------------------------------------------
__global__ __launch_bounds__(256, 2)
void proj_kernel(const float* __restrict__ q, const float* __restrict__ k, const float* __restrict__ v,
                 const float* __restrict__ Wq, const float* __restrict__ Wk, const float* __restrict__ Wv,
                 const float* __restrict__ bq, const float* __restrict__ bk, const float* __restrict__ bv,
                 const float* __restrict__ qcos, const float* __restrict__ qsin,
                 const float* __restrict__ kcos, const float* __restrict__ ksin)
{
    const int z = blockIdx.z;
    const float* X    = (z == 0) ? q  : (z == 1) ? k  : v;
    const float* W    = (z == 0) ? Wq : (z == 1) ? Wk : Wv;
    const float* bias = (z == 0) ? bq : (z == 1) ? bk : bv;
    const float* ct   = (z == 0) ? qcos : kcos;
    const float* st   = (z == 0) ? qsin : ksin;
    float* out = g_proj[z];

    __shared__ float As[16][128];   // [k][m] transposed
    __shared__ float Bs[16][128];   // [k][n] transposed

    const int tid = threadIdx.x;
    const int tx = tid & 15;
    const int ty = tid >> 4;
    const int row0 = blockIdx.y * 128;
    const int col0 = blockIdx.x * 128;

    // per-thread load coordinates (2 float4 per buffer)
    int lr[2], lc[2];
    #pragma unroll
    for (int l = 0; l < 2; l++) {
        int f = tid + l * 256;
        lr[l] = f >> 2;
        lc[l] = (f & 3) << 2;
    }

    u64 acc2[8][4];                 // 8 rows x 4 col-pairs
    #pragma unroll
    for (int i = 0; i < 8; i++)
        #pragma unroll
        for (int j = 0; j < 4; j++)
            acc2[i][j] = 0ull;

    // prefetch kt = 0
    float4 a_pf[2], b_pf[2];
    #pragma unroll
    for (int l = 0; l < 2; l++) {
        a_pf[l] = *(const float4*)&X[(size_t)(row0 + lr[l]) * CC + lc[l]];
        b_pf[l] = *(const float4*)&W[(size_t)(col0 + lr[l]) * CC + lc[l]];
    }

    for (int kt = 0; kt < CC; kt += 16) {
        __syncthreads();   // previous compute finished reading smem
        #pragma unroll
        for (int l = 0; l < 2; l++) {
            int r = lr[l], c4 = lc[l];
            As[c4 + 0][r] = a_pf[l].x; As[c4 + 1][r] = a_pf[l].y;
            As[c4 + 2][r] = a_pf[l].z; As[c4 + 3][r] = a_pf[l].w;
            Bs[c4 + 0][r] = b_pf[l].x; Bs[c4 + 1][r] = b_pf[l].y;
            Bs[c4 + 2][r] = b_pf[l].z; Bs[c4 + 3][r] = b_pf[l].w;
        }
        __syncthreads();

        // prefetch next step (overlaps with compute below)
        if (kt + 16 < CC) {
            #pragma unroll
            for (int l = 0; l < 2; l++) {
                a_pf[l] = *(const float4*)&X[(size_t)(row0 + lr[l]) * CC + kt + 16 + lc[l]];
                b_pf[l] = *(const float4*)&W[(size_t)(col0 + lr[l]) * CC + kt + 16 + lc[l]];
            }
        }

        #pragma unroll
        for (int kk = 0; kk < 16; kk++) {
            float af[8];
            *(float4*)&af[0] = *(const float4*)&As[kk][ty * 8];
            *(float4*)&af[4] = *(const float4*)&As[kk][ty * 8 + 4];
            // B pairs pre-packed in smem (contiguous, 16B aligned): 2x LDS.128
            float4 bf0 = *(const float4*)&Bs[kk][tx * 8];
            float4 bf1 = *(const float4*)&Bs[kk][tx * 8 + 4];
            u64 b2[4] = {f4lo(bf0), f4hi(bf0), f4lo(bf1), f4hi(bf1)};
            #pragma unroll
            for (int i = 0; i < 8; i++) {
                u64 aa = pk2(af[i], af[i]);
                fma2(acc2[i][0], aa, b2[0]);
                fma2(acc2[i][1], aa, b2[1]);
                fma2(acc2[i][2], aa, b2[2]);
                fma2(acc2[i][3], aa, b2[3]);
            }
        }
    }

    // Epilogue: bias, optional RoPE (pairs are within this thread's 8 cols), store.
    const int cbase = col0 + tx * 8;
    const int jbase = (tx * 4) & 31;   // ((cbase % 64) / 2), cbase % 8 == 0
    #pragma unroll
    for (int i = 0; i < 8; i++) {
        int r = row0 + ty * 8 + i;
        int n = r & (NN - 1);
        float vals[8];
        #pragma unroll
        for (int j4 = 0; j4 < 4; j4++)
            upk2(vals[2 * j4], vals[2 * j4 + 1], acc2[i][j4]);
        #pragma unroll
        for (int j = 0; j < 8; j++) vals[j] += bias[cbase + j];
        if (z < 2) {
            #pragma unroll
            for (int jp = 0; jp < 4; jp++) {
                int jj = jbase + jp;
                float c = ct[n * 32 + jj];
                float s = st[n * 32 + jj];
                float xr = vals[2 * jp], xi = vals[2 * jp + 1];
                vals[2 * jp]     = xr * c - xi * s;
                vals[2 * jp + 1] = xr * s + xi * c;
            }
        }
        *(float4*)&out[(size_t)r * CC + cbase]     = make_float4(vals[0], vals[1], vals[2], vals[3]);
        *(float4*)&out[(size_t)r * CC + cbase + 4] = make_float4(vals[4], vals[5], vals[6], vals[7]);
    }
}

// ---------------------------------------------------------------------------
// Kernel 2: flash attention, fp32 + f32x2. 64x64 tiles, hd=64.
// 256 threads (16x16), 4x4 micro-tile. Online softmax with 16-lane shfl.
// smem: qsT[d][m], ksT[d][kn] (aliased as P[m][kn] after S), vs[kn][d]  = 48KB.
// Software-pipelined: K/V loads for tile t+1 issued before compute of t.
// ---------------------------------------------------------------------------
__global__ __launch_bounds__(256, 2)
void attn_kernel(float* __restrict__ out)
{
    __shared__ float qsT[64][64];
    __shared__ float ksT[64][64];   // reused as P[row][kn] between barriers
    __shared__ float vsm[64][64];

    const int tid = threadIdx.x;
    const int tx = tid & 15;
    const int ty = tid >> 4;
    const int m0 = blockIdx.x * 64;
    const int b  = blockIdx.y >> 4;
    const int h  = blockIdx.y & 15;

    const float* Q = g_proj[0];
    const float* K = g_proj[1];
    const float* V = g_proj[2];
    const size_t headoff = (size_t)b * NN * CC + h * HD;

    // per-thread load coordinates (4 float4 per buffer)
    int lr[4], ld[4];
    #pragma unroll
    for (int l = 0; l < 4; l++) {
        int f = tid + l * 256;
        lr[l] = f >> 4;
        ld[l] = (f & 15) << 2;
    }

    // Load Q tile transposed: qsT[d][r] = Q[m0+r][d]
    #pragma unroll
    for (int l = 0; l < 4; l++) {
        int r = lr[l], d4 = ld[l];
        float4 a = *(const float4*)&Q[headoff + (size_t)(m0 + r) * CC + d4];
        qsT[d4 + 0][r] = a.x; qsT[d4 + 1][r] = a.y; qsT[d4 + 2][r] = a.z; qsT[d4 + 3][r] = a.w;
    }

    float m_i[4], l_i[4];
    u64 o2[4][2];
    #pragma unroll
    for (int i = 0; i < 4; i++) {
        m_i[i] = NEGINF; l_i[i] = 0.f;
        o2[i][0] = 0ull; o2[i][1] = 0ull;
    }

    // prefetch tile 0
    float4 k_pf[4], v_pf[4];
    #pragma unroll
    for (int l = 0; l < 4; l++) {
        k_pf[l] = *(const float4*)&K[headoff + (size_t)lr[l] * CC + ld[l]];
        v_pf[l] = *(const float4*)&V[headoff + (size_t)lr[l] * CC + ld[l]];
    }

    for (int t = 0; t < NN / 64; t++) {
        __syncthreads();   // previous PV reads (and Q-store at t=0) done before overwrite
        #pragma unroll
        for (int l = 0; l < 4; l++) {
            int r = lr[l], d4 = ld[l];
            ksT[d4 + 0][r] = k_pf[l].x; ksT[d4 + 1][r] = k_pf[l].y;
            ksT[d4 + 2][r] = k_pf[l].z; ksT[d4 + 3][r] = k_pf[l].w;
            *(float4*)&vsm[r][d4] = v_pf[l];
        }
        __syncthreads();

        // prefetch next tile (overlaps all compute below)
        if (t + 1 < NN / 64) {
            const int kn1 = (t + 1) * 64;
            #pragma unroll
            for (int l = 0; l < 4; l++) {
                k_pf[l] = *(const float4*)&K[headoff + (size_t)(kn1 + lr[l]) * CC + ld[l]];
                v_pf[l] = *(const float4*)&V[headoff + (size_t)(kn1 + lr[l]) * CC + ld[l]];
            }
        }

        // S = Q K^T (4x4 per thread, packed along columns)
        u64 s2[4][2];
        #pragma unroll
        for (int i = 0; i < 4; i++) { s2[i][0] = 0ull; s2[i][1] = 0ull; }

        #pragma unroll 8
        for (int d = 0; d < 64; d++) {
            float4 qf = *(const float4*)&qsT[d][ty * 4];   // LDS.128
            float4 kf = *(const float4*)&ksT[d][tx * 4];   // LDS.128
            u64 k0 = f4lo(kf), k1 = f4hi(kf);
            u64 a0 = pk2(qf.x, qf.x);
            u64 a1 = pk2(qf.y, qf.y);
            u64 a2 = pk2(qf.z, qf.z);
            u64 a3 = pk2(qf.w, qf.w);
            fma2(s2[0][0], a0, k0); fma2(s2[0][1], a0, k1);
            fma2(s2[1][0], a1, k0); fma2(s2[1][1], a1, k1);
            fma2(s2[2][0], a2, k0); fma2(s2[2][1], a2, k1);
            fma2(s2[3][0], a3, k0); fma2(s2[3][1], a3, k1);
        }

        // unpack S, online softmax (row groups = 16 lanes with same ty)
        float s[4][4];
        #pragma unroll
        for (int i = 0; i < 4; i++) {
            upk2(s[i][0], s[i][1], s2[i][0]);
            upk2(s[i][2], s[i][3], s2[i][1]);
        }
        #pragma unroll
        for (int i = 0; i < 4; i++) {
            float rm = NEGINF;
            #pragma unroll
            for (int j = 0; j < 4; j++) { s[i][j] *= SCALE; rm = fmaxf(rm, s[i][j]); }
            #pragma unroll
            for (int off = 8; off > 0; off >>= 1)
                rm = fmaxf(rm, __shfl_xor_sync(0xffffffffu, rm, off));
            float mnew  = fmaxf(m_i[i], rm);
            float alpha = __expf(m_i[i] - mnew);
            float rs = 0.f;
            #pragma unroll
            for (int j = 0; j < 4; j++) { float p = __expf(s[i][j] - mnew); s[i][j] = p; rs += p; }
            #pragma unroll
            for (int off = 8; off > 0; off >>= 1)
                rs += __shfl_xor_sync(0xffffffffu, rs, off);
            l_i[i] = l_i[i] * alpha + rs;
            m_i[i] = mnew;
            u64 al = pk2(alpha, alpha);
            o2[i][0] = mul2(o2[i][0], al);
            o2[i][1] = mul2(o2[i][1], al);
        }
        __syncthreads();   // all S-reads of ksT complete

        // P -> smem (alias ksT), natural layout P[row][kn], float4 stores
        #pragma unroll
        for (int i = 0; i < 4; i++)
            *(float4*)&ksT[4 * ty + i][4 * tx] = make_float4(s[i][0], s[i][1], s[i][2], s[i][3]);
        __syncthreads();

        // O += P V (packed along d-columns)
        #pragma unroll 4
        for (int kb = 0; kb < 16; kb++) {
            float pr[4][4];
            #pragma unroll
            for (int i = 0; i < 4; i++) {
                float4 pf = *(const float4*)&ksT[4 * ty + i][kb * 4];
                pr[i][0] = pf.x; pr[i][1] = pf.y; pr[i][2] = pf.z; pr[i][3] = pf.w;
            }
            #pragma unroll
            for (int u = 0; u < 4; u++) {
                float4 vf = *(const float4*)&vsm[kb * 4 + u][4 * tx];   // LDS.128
                u64 v0 = f4lo(vf), v1 = f4hi(vf);
                #pragma unroll
                for (int i = 0; i < 4; i++) {
                    u64 pp = pk2(pr[i][u], pr[i][u]);
                    fma2(o2[i][0], pp, v0);
                    fma2(o2[i][1], pp, v1);
                }
            }
        }
    }

    // finalize: O /= l, write [B,N,H*hd]
    #pragma unroll
    for (int i = 0; i < 4; i++) {
        float inv = 1.0f / l_i[i];
        u64 iv = pk2(inv, inv);
        u64 r0 = mul2(o2[i][0], iv);
        u64 r1 = mul2(o2[i][1], iv);
        float o0, o1, oc, o3;
        upk2(o0, o1, r0);
        upk2(oc, o3, r1);
        *(float4*)&out[headoff + (size_t)(m0 + 4 * ty + i) * CC + 4 * tx] =
            make_float4(o0, o1, oc, o3);
    }
}

// ---------------------------------------------------------------------------
// Inputs (metadata order): q,k,v,q_cos,q_sin,k_cos,k_sin,Wq,bq,Wk,bk,Wv,bv
// ---------------------------------------------------------------------------
extern "C" void kernel_launch(void* const* d_in, const int* in_sizes, int n_in,
                              void* d_out, int out_size)
{
    (void)in_sizes; (void)n_in; (void)out_size;
    const float* q    = (const float*)d_in[0];
    const float* k    = (const float*)d_in[1];
    const float* v    = (const float*)d_in[2];
    const float* qcos = (const float*)d_in[3];
    const float* qsin = (const float*)d_in[4];
    const float* kcos = (const float*)d_in[5];
    const float* ksin = (const float*)d_in[6];
    const float* Wq   = (const float*)d_in[7];
    const float* bq   = (const float*)d_in[8];
    const float* Wk   = (const float*)d_in[9];
    const float* bk   = (const float*)d_in[10];
    const float* Wv   = (const float*)d_in[11];
    const float* bv   = (const float*)d_in[12];
    float* out = (float*)d_out;

    dim3 gp(CC / 128, MROWS / 128, 3);      // (8, 32, 3)
    proj_kernel<<<gp, 256>>>(q, k, v, Wq, Wk, Wv, bq, bk, bv, qcos, qsin, kcos, ksin);

    dim3 ga(NN / 64, BB * HH);              // (32, 32)
    attn_kernel<<<ga, 256>>>(out);
}